// round 11
// baseline (speedup 1.0000x reference)
#include <cuda_runtime.h>
#include <math.h>
#include <stdint.h>

typedef unsigned long long u64;

#define T_STEPS 1024
#define BATCH   64
#define DIM     512
#define G3      1536
#define NCTA    128
#define TPB     256
#define PTPB    256
#define RPC     32            // rows per CTA
#define UPCC    8             // units per CTA
#define HCH     132           // floats per staged h row (pad 4: conflict-free 4-phase LDS.128)
#define WKS     512           // floats per weight column
#define NCOLS   (UPCC * 9)    // 72 weight columns per CTA

// ---------------- device scratch ----------------
__device__ float g_xg0[(size_t)T_STEPS * G3 * BATCH];   // [t][g][b]
__device__ float g_h0[2][BATCH * DIM];
__device__ float g_h1[2][BATCH * DIM];
__device__ unsigned g_count;
__device__ volatile unsigned g_gen;

#define FMA2(acc, a, b) \
    asm("fma.rn.f32x2 %0, %1, %2, %3;" : "=l"(acc) : "l"(a), "l"(b), "l"(acc))

__device__ __forceinline__ float sum2(u64 v) {
    return __uint_as_float((unsigned)v) + __uint_as_float((unsigned)(v >> 32));
}
__device__ __forceinline__ float sigf(float x) { return 1.f / (1.f + expf(-x)); }

// cp.async 16B
__device__ __forceinline__ void cpa16(uint32_t dst, const float* src) {
    asm volatile("cp.async.cg.shared.global [%0], [%1], 16;" :: "r"(dst), "l"(src) : "memory");
}
#define CP_COMMIT() asm volatile("cp.async.commit_group;" ::: "memory")
#define CP_WAIT0()  asm volatile("cp.async.wait_group 0;" ::: "memory")

// ---------------- grid-wide barrier (128 CTAs, 1/SM by smem) ----------------
__device__ __forceinline__ void gbar(unsigned target) {
    __threadfence();
    __syncthreads();
    if (threadIdx.x == 0) {
        unsigned arrived = atomicAdd(&g_count, 1u);
        if (arrived == NCTA - 1) {
            g_count = 0;
            __threadfence();
            atomicAdd((unsigned*)&g_gen, 1u);
        } else {
            while (g_gen < target) { }
        }
    }
    __syncthreads();
}

// ---------------- phase 1: XG0[t][g][b] = x @ W0 + bi0  (FMA2) ----------------
__global__ void __launch_bounds__(PTPB) precompute_xg0(const float* __restrict__ x,
                                                       const float* __restrict__ W0,
                                                       const float* __restrict__ b0) {
    __shared__ __align__(16) float  xs[32 * 68];
    __shared__ __align__(16) float2 wsd[32 * 66];

    const int t     = blockIdx.y;
    const int gbase = blockIdx.x * 64;
    const int tid   = threadIdx.x;

    if (blockIdx.x == 0 && blockIdx.y == 0) {      // per-replay state reset
        if (tid == 0) { g_count = 0; g_gen = 0; }
        for (int j = tid; j < BATCH * DIM; j += PTPB) {
            g_h0[1][j] = 0.0f;
            g_h1[0][j] = 0.0f;
            g_h1[1][j] = 0.0f;
        }
    }

    const int tr = tid & 15, tc = tid >> 4;
    const int r0 = tr * 4, c0 = tc * 4;

    u64 acc[2][4] = {};

    for (int kc = 0; kc < DIM; kc += 32) {
#pragma unroll
        for (int j = 0; j < 8; ++j) {
            int lin = tid + j * PTPB;
            int bb = lin >> 5, klx = lin & 31;
            xs[klx * 68 + bb] =
                x[(size_t)bb * (T_STEPS * DIM) + (size_t)t * DIM + kc + klx];
            int kk = lin >> 6, cc = lin & 63;
            float w = W0[(size_t)(kc + kk) * G3 + gbase + cc];
            wsd[kk * 66 + cc] = make_float2(w, w);
        }
        __syncthreads();
        const u64* xp = (const u64*)xs;
        const ulonglong2* wp = (const ulonglong2*)wsd;
#pragma unroll
        for (int kk = 0; kk < 32; ++kk) {
            u64 a0 = xp[kk * 34 + tr * 2];
            u64 a1 = xp[kk * 34 + tr * 2 + 1];
            ulonglong2 w01 = wp[kk * 33 + tc * 2];
            ulonglong2 w23 = wp[kk * 33 + tc * 2 + 1];
            FMA2(acc[0][0], a0, w01.x); FMA2(acc[0][1], a0, w01.y);
            FMA2(acc[0][2], a0, w23.x); FMA2(acc[0][3], a0, w23.y);
            FMA2(acc[1][0], a1, w01.x); FMA2(acc[1][1], a1, w01.y);
            FMA2(acc[1][2], a1, w23.x); FMA2(acc[1][3], a1, w23.y);
        }
        __syncthreads();
    }

    float4 bias = *(const float4*)&b0[gbase + c0];
    float bi[4] = {bias.x, bias.y, bias.z, bias.w};
#pragma unroll
    for (int rp = 0; rp < 2; ++rp) {
#pragma unroll
        for (int i = 0; i < 4; ++i) {
            float2 v;
            v.x = __uint_as_float((unsigned)acc[rp][i]) + bi[i];
            v.y = __uint_as_float((unsigned)(acc[rp][i] >> 32)) + bi[i];
            size_t o = ((size_t)t * G3 + gbase + c0 + i) * BATCH + r0 + 2 * rp;
            *(float2*)&g_xg0[o] = v;
        }
    }
}

// ---------------- phase 2: persistent loop, 4x9 register tile, k-split 4 -------
// CTA = 8 units x 32 rows. warp = unit; lane = (rg 0..7, kid 0..3).
// Thread tile: rows {rg+8*r, r=0..3} x 9 dots of unit `warp`; k-quads it*4+kid.
// acc[36] u64 (72 regs) -> no spills. Shuffle-reduce over kid (2 rounds);
// thread kid takes r_it = kid -> pointwise row rg + 8*kid.
#define SMEM_FLOATS (NCOLS * WKS + 4 * RPC * HCH)
#define SMEM_BYTES  (SMEM_FLOATS * 4)    // 215,040 B

__global__ void __launch_bounds__(TPB, 1)
gru_loop(const float* __restrict__ U0, const float* __restrict__ W1,
         const float* __restrict__ U1, const float* __restrict__ b0,
         const float* __restrict__ b1, float* __restrict__ out) {
    extern __shared__ __align__(16) float sm[];
    float* ws = sm;                                   // [72][512]
    float* hb0[2] = { sm + NCOLS * WKS,
                      sm + NCOLS * WKS + RPC * HCH };
    float* hb1[2] = { sm + NCOLS * WKS + 2 * RPC * HCH,
                      sm + NCOLS * WKS + 3 * RPC * HCH };
    const uint32_t hb0u0 = (uint32_t)__cvta_generic_to_shared(hb0[0]);
    const uint32_t hb0u1 = (uint32_t)__cvta_generic_to_shared(hb0[1]);
    const uint32_t hb1u0 = (uint32_t)__cvta_generic_to_shared(hb1[0]);
    const uint32_t hb1u1 = (uint32_t)__cvta_generic_to_shared(hb1[1]);

    const int tid   = threadIdx.x;
    const int lane  = tid & 31;
    const int cg    = tid >> 5;          // warp = unit 0..7
    const int kid   = lane & 3;          // k-split id
    const int rg    = lane >> 2;         // rowgroup 0..7
    const int ubase = (blockIdx.x >> 1) * UPCC;
    const int rbase = (blockIdx.x & 1) * RPC;
    const int ug    = ubase + cg;
    const int row   = rbase + rg + 8 * kid;   // this thread's pointwise row

    // one-time weight preload: col c = cg*9 + j; j 0-2:U0 z/r/h, 3-5:U1, 6-8:W1
    for (int idx = tid; idx < NCOLS * DIM; idx += TPB) {
        int c = idx >> 9, k = idx & 511;
        int uu = c / 9, j = c % 9;
        const float* mat = (j < 3) ? U0 : (j < 6 ? U1 : W1);
        int gate = j % 3;
        ws[c * WKS + k] = __ldg(mat + (size_t)k * G3 + gate * 512 + ubase + uu);
    }
    const float br0z = b0[G3 + ug], br0r = b0[G3 + 512 + ug], br0h = b0[G3 + 1024 + ug];
    const float bi1z = b1[ug],      bi1r = b1[512 + ug],      bi1h = b1[1024 + ug];
    const float br1z = b1[G3 + ug], br1r = b1[G3 + 512 + ug], br1h = b1[G3 + 1024 + ug];
    __syncthreads();

    const float* wbase = ws + (size_t)cg * 9 * WKS;
    unsigned gen = 0;

    for (int t = 0; t <= T_STEPS; ++t) {
        const float* h0in  = g_h0[(t + 1) & 1];   // h0(t-1)
        const float* h1in  = g_h1[(t + 1) & 1];   // h1(t-2)
        float*       h0out = g_h0[t & 1];
        float*       h1out = g_h1[t & 1];

        // ---- stage chunk 0 via cp.async ----
#pragma unroll
        for (int j = 0; j < 8; ++j) {
            int idx = tid + j * TPB;
            int arr = idx >> 10, rem = idx & 1023;
            int rr = rem >> 5, k4 = rem & 31;
            const float* src = (arr ? h1in : h0in) + (rbase + rr) * 512 + k4 * 4;
            uint32_t dst = (arr ? hb1u0 : hb0u0) + (uint32_t)(rr * HCH + k4 * 4) * 4u;
            cpa16(dst, src);
        }
        CP_COMMIT();

        // gate-input prefetch (hidden behind the dots)
        float xz = 0.f, xr = 0.f, xh = 0.f, h0o = 0.f, h1o = 0.f;
        if (t < T_STEPS) {
            size_t xb = ((size_t)t * G3 + ug) * BATCH + row;
            xz  = __ldg(&g_xg0[xb]);
            xr  = __ldg(&g_xg0[xb + 512 * BATCH]);
            xh  = __ldg(&g_xg0[xb + 1024 * BATCH]);
            h0o = __ldcg(h0in + row * 512 + ug);
        }
        if (t >= 1) h1o = __ldcg(h1in + row * 512 + ug);

        CP_WAIT0();
        __syncthreads();

        // ---- 4x9 register tile over 4 chunks; kid owns k-quads it*4+kid ----
        u64 acc[36] = {};   // [r*9 + j], k-pair packed
#pragma unroll
        for (int kc = 0; kc < 4; ++kc) {
            if (kc < 3) {   // async-stage next chunk into the other buffer
                uint32_t d0 = (kc & 1) ? hb0u0 : hb0u1;
                uint32_t d1 = (kc & 1) ? hb1u0 : hb1u1;
#pragma unroll
                for (int j = 0; j < 8; ++j) {
                    int idx = tid + j * TPB;
                    int arr = idx >> 10, rem = idx & 1023;
                    int rr = rem >> 5, k4 = rem & 31;
                    const float* src = (arr ? h1in : h0in) +
                                       (rbase + rr) * 512 + (kc + 1) * 128 + k4 * 4;
                    uint32_t dst = (arr ? d1 : d0) + (uint32_t)(rr * HCH + k4 * 4) * 4u;
                    cpa16(dst, src);
                }
                CP_COMMIT();
            }

            const float* hc0 = hb0[kc & 1];
            const float* hc1 = hb1[kc & 1];
            const float* wk  = wbase + kc * 128;
#pragma unroll
            for (int it = 0; it < 8; ++it) {
                int ko = (it * 4 + kid) * 4;          // float offset of this k-quad
                ulonglong2 W[9];
#pragma unroll
                for (int j = 0; j < 9; ++j)
                    W[j] = *(const ulonglong2*)(wk + j * WKS + ko);
#pragma unroll
                for (int r = 0; r < 4; ++r) {
                    int hrow = rg + 8 * r;
                    ulonglong2 h0v = *(const ulonglong2*)(hc0 + hrow * HCH + ko);
                    ulonglong2 h1v = *(const ulonglong2*)(hc1 + hrow * HCH + ko);
#pragma unroll
                    for (int j = 0; j < 9; ++j) {
                        const bool useh1 = (j >= 3 && j < 6);
                        u64 alo = useh1 ? h1v.x : h0v.x;
                        u64 ahi = useh1 ? h1v.y : h0v.y;
                        FMA2(acc[r * 9 + j], alo, W[j].x);
                        FMA2(acc[r * 9 + j], ahi, W[j].y);
                    }
                }
            }

            if (kc < 3) {
                CP_WAIT0();
                __syncthreads();
            }
        }

        // ---- reduce k-split over kid (2 shuffle rounds within lane quads) ----
        float vr[4][9];
#pragma unroll
        for (int r = 0; r < 4; ++r)
#pragma unroll
            for (int j = 0; j < 9; ++j) vr[r][j] = sum2(acc[r * 9 + j]);

#pragma unroll
        for (int B = 1; B <= 2; B <<= 1) {
#pragma unroll
            for (int r = 0; r < 4; ++r)
#pragma unroll
                for (int j = 0; j < 9; ++j) {
                    float o = __shfl_xor_sync(0xffffffffu, vr[r][j], B);
                    if (((r ^ kid) & B) == 0) vr[r][j] += o;
                }
        }
        float s[9];
#pragma unroll
        for (int r = 0; r < 4; ++r)
            if (r == kid) {
#pragma unroll
                for (int j = 0; j < 9; ++j) s[j] = vr[r][j];
            }

        // ---- pointwise layer 0: h0(t) ----
        if (t < T_STEPS) {
            float z    = sigf(xz + s[0] + br0z);
            float rgt  = sigf(xr + s[1] + br0r);
            float cand = tanhf(xh + rgt * (s[2] + br0h));
            h0out[row * 512 + ug] = z * h0o + (1.f - z) * cand;
        }
        // ---- pointwise layer 1: h1(t-1) ----
        if (t >= 1) {
            float z1    = sigf(s[6] + bi1z + s[3] + br1z);
            float r1    = sigf(s[7] + bi1r + s[4] + br1r);
            float cand1 = tanhf(s[8] + bi1h + r1 * (s[5] + br1h));
            float h1n   = z1 * h1o + (1.f - z1) * cand1;
            h1out[row * 512 + ug] = h1n;
            if (t == T_STEPS) out[row * 512 + ug] = h1n;
        }

        gbar(++gen);
    }
}

// ---------------- launcher ----------------
extern "C" void kernel_launch(void* const* d_in, const int* in_sizes, int n_in,
                              void* d_out, int out_size) {
    const float* x  = (const float*)d_in[0];
    const float* W0 = (const float*)d_in[1];
    const float* U0 = (const float*)d_in[2];
    const float* b0 = (const float*)d_in[3];
    const float* W1 = (const float*)d_in[4];
    const float* U1 = (const float*)d_in[5];
    const float* b1 = (const float*)d_in[6];
    float* out = (float*)d_out;

    cudaFuncSetAttribute(gru_loop, cudaFuncAttributeMaxDynamicSharedMemorySize,
                         SMEM_BYTES);

    precompute_xg0<<<dim3(24, 1024), PTPB>>>(x, W0, b0);
    gru_loop<<<NCTA, TPB, SMEM_BYTES>>>(U0, W1, U1, b0, b1, out);
}

// round 12
// speedup vs baseline: 1.1551x; 1.1551x over previous
#include <cuda_runtime.h>
#include <math.h>
#include <stdint.h>

typedef unsigned long long u64;

#define T_STEPS 1024
#define BATCH   64
#define DIM     512
#define G3      1536
#define NCTA    128
#define TPB     512           // gru_loop: 16 warps
#define PTPB    256
#define RPC     32            // rows per CTA
#define UPCC    8             // units per CTA
#define HCH     128           // floats per staged h row (mult of 32 -> row term drops from banks)
#define WKS     512           // floats per weight column (mult of 32)
#define NCOLS   (UPCC * 9)    // 72 weight columns per CTA

// ---------------- device scratch ----------------
__device__ float g_xg0[(size_t)T_STEPS * G3 * BATCH];   // [t][g][b]
__device__ float g_h0[2][BATCH * DIM];
__device__ float g_h1[2][BATCH * DIM];
__device__ unsigned g_count;
__device__ volatile unsigned g_gen;

#define FMA2(acc, a, b) \
    asm("fma.rn.f32x2 %0, %1, %2, %3;" : "=l"(acc) : "l"(a), "l"(b), "l"(acc))

__device__ __forceinline__ float sum2(u64 v) {
    return __uint_as_float((unsigned)v) + __uint_as_float((unsigned)(v >> 32));
}
__device__ __forceinline__ float sigf(float x) { return 1.f / (1.f + expf(-x)); }

// cp.async 16B
__device__ __forceinline__ void cpa16(uint32_t dst, const float* src) {
    asm volatile("cp.async.cg.shared.global [%0], [%1], 16;" :: "r"(dst), "l"(src) : "memory");
}
#define CP_COMMIT() asm volatile("cp.async.commit_group;" ::: "memory")
#define CP_WAIT0()  asm volatile("cp.async.wait_group 0;" ::: "memory")

// ---------------- grid-wide barrier (128 CTAs, 1/SM by smem) ----------------
__device__ __forceinline__ void gbar(unsigned target) {
    __threadfence();
    __syncthreads();
    if (threadIdx.x == 0) {
        unsigned arrived = atomicAdd(&g_count, 1u);
        if (arrived == NCTA - 1) {
            g_count = 0;
            __threadfence();
            atomicAdd((unsigned*)&g_gen, 1u);
        } else {
            while (g_gen < target) { }
        }
    }
    __syncthreads();
}

// ---------------- phase 1: XG0[t][g][b] = x @ W0 + bi0  (FMA2) ----------------
__global__ void __launch_bounds__(PTPB) precompute_xg0(const float* __restrict__ x,
                                                       const float* __restrict__ W0,
                                                       const float* __restrict__ b0) {
    __shared__ __align__(16) float  xs[32 * 68];
    __shared__ __align__(16) float2 wsd[32 * 66];

    const int t     = blockIdx.y;
    const int gbase = blockIdx.x * 64;
    const int tid   = threadIdx.x;

    if (blockIdx.x == 0 && blockIdx.y == 0) {      // per-replay state reset
        if (tid == 0) { g_count = 0; g_gen = 0; }
        for (int j = tid; j < BATCH * DIM; j += PTPB) {
            g_h0[1][j] = 0.0f;
            g_h1[0][j] = 0.0f;
            g_h1[1][j] = 0.0f;
        }
    }

    const int tr = tid & 15, tc = tid >> 4;
    const int r0 = tr * 4, c0 = tc * 4;

    u64 acc[2][4] = {};

    for (int kc = 0; kc < DIM; kc += 32) {
#pragma unroll
        for (int j = 0; j < 8; ++j) {
            int lin = tid + j * PTPB;
            int bb = lin >> 5, klx = lin & 31;
            xs[klx * 68 + bb] =
                x[(size_t)bb * (T_STEPS * DIM) + (size_t)t * DIM + kc + klx];
            int kk = lin >> 6, cc = lin & 63;
            float w = W0[(size_t)(kc + kk) * G3 + gbase + cc];
            wsd[kk * 66 + cc] = make_float2(w, w);
        }
        __syncthreads();
        const u64* xp = (const u64*)xs;
        const ulonglong2* wp = (const ulonglong2*)wsd;
#pragma unroll
        for (int kk = 0; kk < 32; ++kk) {
            u64 a0 = xp[kk * 34 + tr * 2];
            u64 a1 = xp[kk * 34 + tr * 2 + 1];
            ulonglong2 w01 = wp[kk * 33 + tc * 2];
            ulonglong2 w23 = wp[kk * 33 + tc * 2 + 1];
            FMA2(acc[0][0], a0, w01.x); FMA2(acc[0][1], a0, w01.y);
            FMA2(acc[0][2], a0, w23.x); FMA2(acc[0][3], a0, w23.y);
            FMA2(acc[1][0], a1, w01.x); FMA2(acc[1][1], a1, w01.y);
            FMA2(acc[1][2], a1, w23.x); FMA2(acc[1][3], a1, w23.y);
        }
        __syncthreads();
    }

    float4 bias = *(const float4*)&b0[gbase + c0];
    float bi[4] = {bias.x, bias.y, bias.z, bias.w};
#pragma unroll
    for (int rp = 0; rp < 2; ++rp) {
#pragma unroll
        for (int i = 0; i < 4; ++i) {
            float2 v;
            v.x = __uint_as_float((unsigned)acc[rp][i]) + bi[i];
            v.y = __uint_as_float((unsigned)(acc[rp][i] >> 32)) + bi[i];
            size_t o = ((size_t)t * G3 + gbase + c0 + i) * BATCH + r0 + 2 * rp;
            *(float2*)&g_xg0[o] = v;
        }
    }
}

// ---------------- phase 2: persistent loop, 4x9 tile, k-split 8, 16 warps ------
// CTA = 8 units x 32 rows. warp wid: unit = wid>>1, rghi = wid&1.
// lane: rglo = lane>>3 (0..3), kid = lane&7. rg = rghi*4+rglo (0..7).
// Thread rows: rg + 8r, r=0..3. k-quads: it*8+kid (4 its/chunk, 4 chunks).
// acc[36] u64 (72 regs); W reloaded per j (transient); H[4][2] live (16 regs).
// Butterfly-reduce over kid (lane bits 0-2); kid 0..3 do pointwise for r=kid.
#define SMEM_FLOATS (NCOLS * WKS + 4 * RPC * HCH)
#define SMEM_BYTES  (SMEM_FLOATS * 4)    // 212,992 B

__global__ void __launch_bounds__(TPB, 1)
gru_loop(const float* __restrict__ U0, const float* __restrict__ W1,
         const float* __restrict__ U1, const float* __restrict__ b0,
         const float* __restrict__ b1, float* __restrict__ out) {
    extern __shared__ __align__(16) float sm[];
    float* ws = sm;                                   // [72][512]
    float* hb0[2] = { sm + NCOLS * WKS,
                      sm + NCOLS * WKS + RPC * HCH };
    float* hb1[2] = { sm + NCOLS * WKS + 2 * RPC * HCH,
                      sm + NCOLS * WKS + 3 * RPC * HCH };
    const uint32_t hb0u0 = (uint32_t)__cvta_generic_to_shared(hb0[0]);
    const uint32_t hb0u1 = (uint32_t)__cvta_generic_to_shared(hb0[1]);
    const uint32_t hb1u0 = (uint32_t)__cvta_generic_to_shared(hb1[0]);
    const uint32_t hb1u1 = (uint32_t)__cvta_generic_to_shared(hb1[1]);

    const int tid   = threadIdx.x;
    const int lane  = tid & 31;
    const int wid   = tid >> 5;
    const int cg    = wid >> 1;                // unit 0..7
    const int rghi  = wid & 1;
    const int rglo  = lane >> 3;               // 0..3
    const int kid   = lane & 7;                // k-split id
    const int rg    = rghi * 4 + rglo;         // rowgroup 0..7
    const int ubase = (blockIdx.x >> 1) * UPCC;
    const int rbase = (blockIdx.x & 1) * RPC;
    const int ug    = ubase + cg;
    const int rsel  = kid & 3;                 // pointwise r for kid<4
    const int row   = rbase + rg + 8 * rsel;   // pointwise row (kid<4 only)

    // one-time weight preload: col c = cg*9 + j; j 0-2:U0 z/r/h, 3-5:U1, 6-8:W1
    for (int idx = tid; idx < NCOLS * DIM; idx += TPB) {
        int c = idx >> 9, k = idx & 511;
        int uu = c / 9, j = c % 9;
        const float* mat = (j < 3) ? U0 : (j < 6 ? U1 : W1);
        int gate = j % 3;
        ws[c * WKS + k] = __ldg(mat + (size_t)k * G3 + gate * 512 + ubase + uu);
    }
    const float br0z = b0[G3 + ug], br0r = b0[G3 + 512 + ug], br0h = b0[G3 + 1024 + ug];
    const float bi1z = b1[ug],      bi1r = b1[512 + ug],      bi1h = b1[1024 + ug];
    const float br1z = b1[G3 + ug], br1r = b1[G3 + 512 + ug], br1h = b1[G3 + 1024 + ug];
    __syncthreads();

    const float* wbase = ws + (size_t)cg * 9 * WKS;
    unsigned gen = 0;

    for (int t = 0; t <= T_STEPS; ++t) {
        const float* h0in  = g_h0[(t + 1) & 1];   // h0(t-1)
        const float* h1in  = g_h1[(t + 1) & 1];   // h1(t-2)
        float*       h0out = g_h0[t & 1];
        float*       h1out = g_h1[t & 1];

        // ---- stage chunk 0 via cp.async: 4 x 16B per thread ----
#pragma unroll
        for (int j = 0; j < 4; ++j) {
            int idx = tid + j * TPB;            // 0..2047
            int arr = idx >> 10, rem = idx & 1023;
            int rr = rem >> 5, k4 = rem & 31;
            const float* src = (arr ? h1in : h0in) + (rbase + rr) * 512 + k4 * 4;
            uint32_t dst = (arr ? hb1u0 : hb0u0) + (uint32_t)(rr * HCH + k4 * 4) * 4u;
            cpa16(dst, src);
        }
        CP_COMMIT();

        // gate-input prefetch (kid<4 lanes; hidden behind the dots)
        float xz = 0.f, xr = 0.f, xh = 0.f, h0o = 0.f, h1o = 0.f;
        if (kid < 4) {
            if (t < T_STEPS) {
                size_t xb = ((size_t)t * G3 + ug) * BATCH + row;
                xz  = __ldg(&g_xg0[xb]);
                xr  = __ldg(&g_xg0[xb + 512 * BATCH]);
                xh  = __ldg(&g_xg0[xb + 1024 * BATCH]);
                h0o = __ldcg(h0in + row * 512 + ug);
            }
            if (t >= 1) h1o = __ldcg(h1in + row * 512 + ug);
        }

        CP_WAIT0();
        __syncthreads();

        // ---- 4x9 register tile; kid owns k-quads it*8+kid (4 its/chunk) ----
        u64 acc[36] = {};   // [r*9 + j], k-pair packed
#pragma unroll
        for (int kc = 0; kc < 4; ++kc) {
            if (kc < 3) {   // async-stage next chunk into the other buffer
                uint32_t d0 = (kc & 1) ? hb0u0 : hb0u1;
                uint32_t d1 = (kc & 1) ? hb1u0 : hb1u1;
#pragma unroll
                for (int j = 0; j < 4; ++j) {
                    int idx = tid + j * TPB;
                    int arr = idx >> 10, rem = idx & 1023;
                    int rr = rem >> 5, k4 = rem & 31;
                    const float* src = (arr ? h1in : h0in) +
                                       (rbase + rr) * 512 + (kc + 1) * 128 + k4 * 4;
                    uint32_t dst = (arr ? d1 : d0) + (uint32_t)(rr * HCH + k4 * 4) * 4u;
                    cpa16(dst, src);
                }
                CP_COMMIT();
            }

            const float* hc0 = hb0[kc & 1];
            const float* hc1 = hb1[kc & 1];
            const float* wk  = wbase + kc * 128;
#pragma unroll
            for (int it = 0; it < 4; ++it) {
                int ko = (it * 8 + kid) * 4;          // float offset of this k-quad
                ulonglong2 h0v[4], h1v[4];
#pragma unroll
                for (int r = 0; r < 4; ++r) {
                    int hrow = rg + 8 * r;
                    h0v[r] = *(const ulonglong2*)(hc0 + hrow * HCH + ko);
                    h1v[r] = *(const ulonglong2*)(hc1 + hrow * HCH + ko);
                }
#pragma unroll
                for (int j = 0; j < 9; ++j) {
                    ulonglong2 W = *(const ulonglong2*)(wk + j * WKS + ko);
                    const bool useh1 = (j >= 3 && j < 6);
#pragma unroll
                    for (int r = 0; r < 4; ++r) {
                        u64 alo = useh1 ? h1v[r].x : h0v[r].x;
                        u64 ahi = useh1 ? h1v[r].y : h0v[r].y;
                        FMA2(acc[r * 9 + j], alo, W.x);
                        FMA2(acc[r * 9 + j], ahi, W.y);
                    }
                }
            }

            if (kc < 3) {
                CP_WAIT0();
                __syncthreads();
            }
        }

        // ---- reduce k-split over kid: full butterfly on lane bits 0-2 ----
        float vr[4][9];
#pragma unroll
        for (int r = 0; r < 4; ++r)
#pragma unroll
            for (int j = 0; j < 9; ++j) vr[r][j] = sum2(acc[r * 9 + j]);
#pragma unroll
        for (int B = 1; B <= 4; B <<= 1) {
#pragma unroll
            for (int r = 0; r < 4; ++r)
#pragma unroll
                for (int j = 0; j < 9; ++j)
                    vr[r][j] += __shfl_xor_sync(0xffffffffu, vr[r][j], B);
        }

        // ---- pointwise (kid 0..3 lanes; r = kid) ----
        if (kid < 4) {
            float s[9];
#pragma unroll
            for (int r = 0; r < 4; ++r)
                if (r == rsel) {
#pragma unroll
                    for (int j = 0; j < 9; ++j) s[j] = vr[r][j];
                }
            if (t < T_STEPS) {
                float z    = sigf(xz + s[0] + br0z);
                float rgt  = sigf(xr + s[1] + br0r);
                float cand = tanhf(xh + rgt * (s[2] + br0h));
                h0out[row * 512 + ug] = z * h0o + (1.f - z) * cand;
            }
            if (t >= 1) {
                float z1    = sigf(s[6] + bi1z + s[3] + br1z);
                float r1    = sigf(s[7] + bi1r + s[4] + br1r);
                float cand1 = tanhf(s[8] + bi1h + r1 * (s[5] + br1h));
                float h1n   = z1 * h1o + (1.f - z1) * cand1;
                h1out[row * 512 + ug] = h1n;
                if (t == T_STEPS) out[row * 512 + ug] = h1n;
            }
        }

        gbar(++gen);
    }
}

// ---------------- launcher ----------------
extern "C" void kernel_launch(void* const* d_in, const int* in_sizes, int n_in,
                              void* d_out, int out_size) {
    const float* x  = (const float*)d_in[0];
    const float* W0 = (const float*)d_in[1];
    const float* U0 = (const float*)d_in[2];
    const float* b0 = (const float*)d_in[3];
    const float* W1 = (const float*)d_in[4];
    const float* U1 = (const float*)d_in[5];
    const float* b1 = (const float*)d_in[6];
    float* out = (float*)d_out;

    cudaFuncSetAttribute(gru_loop, cudaFuncAttributeMaxDynamicSharedMemorySize,
                         SMEM_BYTES);

    precompute_xg0<<<dim3(24, 1024), PTPB>>>(x, W0, b0);
    gru_loop<<<NCTA, TPB, SMEM_BYTES>>>(U0, W1, U1, b0, b1, out);
}

// round 13
// speedup vs baseline: 1.4067x; 1.2178x over previous
#include <cuda_runtime.h>
#include <math.h>
#include <stdint.h>

typedef unsigned long long u64;

#define T_STEPS 1024
#define BATCH   64
#define DIM     512
#define G3      1536
#define NCTA    128
#define TPB     256
#define PTPB    256
#define RPC     32            // rows per CTA
#define UPCC    8             // units per CTA
#define HCH     128           // floats per staged h row (mult of 32)
#define WKS     512           // floats per weight column (mult of 32)
#define NCOLS   (UPCC * 9)    // 72 weight columns per CTA

// ---------------- device scratch ----------------
__device__ float g_xg0[(size_t)T_STEPS * G3 * BATCH];   // [t][g][b]
__device__ float g_h0[2][BATCH * DIM];
__device__ float g_h1[2][BATCH * DIM];
__device__ unsigned g_count;
__device__ unsigned g_gen;

#define FMA2(acc, a, b) \
    asm("fma.rn.f32x2 %0, %1, %2, %3;" : "=l"(acc) : "l"(a), "l"(b), "l"(acc))

__device__ __forceinline__ float sum2(u64 v) {
    return __uint_as_float((unsigned)v) + __uint_as_float((unsigned)(v >> 32));
}
__device__ __forceinline__ float sigf(float x) { return 1.f / (1.f + expf(-x)); }

// cp.async 16B
__device__ __forceinline__ void cpa16(uint32_t dst, const float* src) {
    asm volatile("cp.async.cg.shared.global [%0], [%1], 16;" :: "r"(dst), "l"(src) : "memory");
}
#define CP_COMMIT() asm volatile("cp.async.commit_group;" ::: "memory")
#define CP_WAIT0()  asm volatile("cp.async.wait_group 0;" ::: "memory")

// ---------------- grid-wide barrier: acq_rel arrive, release publish, acquire poll
__device__ __forceinline__ void gbar(unsigned target) {
    __syncthreads();
    if (threadIdx.x == 0) {
        unsigned arrived;
        asm volatile("atom.acq_rel.gpu.global.add.u32 %0, [%1], 1;"
                     : "=r"(arrived) : "l"(&g_count) : "memory");
        if (arrived == NCTA - 1) {
            g_count = 0;   // safe: everyone else is spinning on g_gen
            asm volatile("red.release.gpu.global.add.u32 [%0], 1;"
                         :: "l"(&g_gen) : "memory");
        } else {
            unsigned g;
            do {
                asm volatile("ld.acquire.gpu.global.u32 %0, [%1];"
                             : "=r"(g) : "l"(&g_gen) : "memory");
            } while (g < target);
        }
    }
    __syncthreads();
}

// ---------------- phase 1: XG0[t][g][b] = x @ W0 + bi0  (FMA2) ----------------
__global__ void __launch_bounds__(PTPB) precompute_xg0(const float* __restrict__ x,
                                                       const float* __restrict__ W0,
                                                       const float* __restrict__ b0) {
    __shared__ __align__(16) float  xs[32 * 68];
    __shared__ __align__(16) float2 wsd[32 * 66];

    const int t     = blockIdx.y;
    const int gbase = blockIdx.x * 64;
    const int tid   = threadIdx.x;

    if (blockIdx.x == 0 && blockIdx.y == 0) {      // per-replay state reset
        if (tid == 0) { g_count = 0; g_gen = 0; }
        for (int j = tid; j < BATCH * DIM; j += PTPB) {
            g_h0[1][j] = 0.0f;
            g_h1[0][j] = 0.0f;
            g_h1[1][j] = 0.0f;
        }
    }

    const int tr = tid & 15, tc = tid >> 4;
    const int r0 = tr * 4, c0 = tc * 4;

    u64 acc[2][4] = {};

    for (int kc = 0; kc < DIM; kc += 32) {
#pragma unroll
        for (int j = 0; j < 8; ++j) {
            int lin = tid + j * PTPB;
            int bb = lin >> 5, klx = lin & 31;
            xs[klx * 68 + bb] =
                x[(size_t)bb * (T_STEPS * DIM) + (size_t)t * DIM + kc + klx];
            int kk = lin >> 6, cc = lin & 63;
            float w = W0[(size_t)(kc + kk) * G3 + gbase + cc];
            wsd[kk * 66 + cc] = make_float2(w, w);
        }
        __syncthreads();
        const u64* xp = (const u64*)xs;
        const ulonglong2* wp = (const ulonglong2*)wsd;
#pragma unroll
        for (int kk = 0; kk < 32; ++kk) {
            u64 a0 = xp[kk * 34 + tr * 2];
            u64 a1 = xp[kk * 34 + tr * 2 + 1];
            ulonglong2 w01 = wp[kk * 33 + tc * 2];
            ulonglong2 w23 = wp[kk * 33 + tc * 2 + 1];
            FMA2(acc[0][0], a0, w01.x); FMA2(acc[0][1], a0, w01.y);
            FMA2(acc[0][2], a0, w23.x); FMA2(acc[0][3], a0, w23.y);
            FMA2(acc[1][0], a1, w01.x); FMA2(acc[1][1], a1, w01.y);
            FMA2(acc[1][2], a1, w23.x); FMA2(acc[1][3], a1, w23.y);
        }
        __syncthreads();
    }

    float4 bias = *(const float4*)&b0[gbase + c0];
    float bi[4] = {bias.x, bias.y, bias.z, bias.w};
#pragma unroll
    for (int rp = 0; rp < 2; ++rp) {
#pragma unroll
        for (int i = 0; i < 4; ++i) {
            float2 v;
            v.x = __uint_as_float((unsigned)acc[rp][i]) + bi[i];
            v.y = __uint_as_float((unsigned)(acc[rp][i] >> 32)) + bi[i];
            size_t o = ((size_t)t * G3 + gbase + c0 + i) * BATCH + r0 + 2 * rp;
            *(float2*)&g_xg0[o] = v;
        }
    }
}

// ---------------- phase 2: persistent loop, 8x9 tile, warp=unit, k-split 8 -----
// CTA = 8 units x 32 rows. warp = unit cg. lane: rgi = lane>>3 (0..3), kid = lane&7.
// Thread tile: rows rgi*8 + r (r=0..7) x 9 dots of unit cg; k-quads it*8+kid.
// Inner: hoist W[9] (36 regs), stream H per row (4 transient). acc[72] u64.
// W-LDS: 1 phase (broadcast); H-LDS: 4 phases (optimal). 25 LDS / 144 FMA2 per it.
// Butterfly over kid (3 rounds); lane kid does pointwise for r = kid.
#define SMEM_FLOATS (NCOLS * WKS + 4 * RPC * HCH)
#define SMEM_BYTES  (SMEM_FLOATS * 4)    // 212,992 B

__global__ void __launch_bounds__(TPB, 1)
gru_loop(const float* __restrict__ U0, const float* __restrict__ W1,
         const float* __restrict__ U1, const float* __restrict__ b0,
         const float* __restrict__ b1, float* __restrict__ out) {
    extern __shared__ __align__(16) float sm[];
    float* ws = sm;                                   // [72][512]
    float* hb0[2] = { sm + NCOLS * WKS,
                      sm + NCOLS * WKS + RPC * HCH };
    float* hb1[2] = { sm + NCOLS * WKS + 2 * RPC * HCH,
                      sm + NCOLS * WKS + 3 * RPC * HCH };
    const uint32_t hb0u0 = (uint32_t)__cvta_generic_to_shared(hb0[0]);
    const uint32_t hb0u1 = (uint32_t)__cvta_generic_to_shared(hb0[1]);
    const uint32_t hb1u0 = (uint32_t)__cvta_generic_to_shared(hb1[0]);
    const uint32_t hb1u1 = (uint32_t)__cvta_generic_to_shared(hb1[1]);

    const int tid   = threadIdx.x;
    const int lane  = tid & 31;
    const int cg    = tid >> 5;                // warp = unit 0..7
    const int rgi   = lane >> 3;               // rowgroup 0..3 (8 rows each)
    const int kid   = lane & 7;                // k-split id
    const int ubase = (blockIdx.x >> 1) * UPCC;
    const int rbase = (blockIdx.x & 1) * RPC;
    const int ug    = ubase + cg;
    const int row   = rbase + rgi * 8 + kid;   // this thread's pointwise row

    // one-time weight preload: col c = cg*9 + j; j 0-2:U0 z/r/h, 3-5:U1, 6-8:W1
    for (int idx = tid; idx < NCOLS * DIM; idx += TPB) {
        int c = idx >> 9, k = idx & 511;
        int uu = c / 9, j = c % 9;
        const float* mat = (j < 3) ? U0 : (j < 6 ? U1 : W1);
        int gate = j % 3;
        ws[c * WKS + k] = __ldg(mat + (size_t)k * G3 + gate * 512 + ubase + uu);
    }
    const float br0z = b0[G3 + ug], br0r = b0[G3 + 512 + ug], br0h = b0[G3 + 1024 + ug];
    const float bi1z = b1[ug],      bi1r = b1[512 + ug],      bi1h = b1[1024 + ug];
    const float br1z = b1[G3 + ug], br1r = b1[G3 + 512 + ug], br1h = b1[G3 + 1024 + ug];
    __syncthreads();

    const float* wbase = ws + (size_t)cg * 9 * WKS;
    unsigned gen = 0;

    for (int t = 0; t <= T_STEPS; ++t) {
        const float* h0in  = g_h0[(t + 1) & 1];   // h0(t-1)
        const float* h1in  = g_h1[(t + 1) & 1];   // h1(t-2)
        float*       h0out = g_h0[t & 1];
        float*       h1out = g_h1[t & 1];

        // ---- stage chunk 0 via cp.async: 8 x 16B per thread ----
#pragma unroll
        for (int j = 0; j < 8; ++j) {
            int idx = tid + j * TPB;            // 0..2047
            int arr = idx >> 10, rem = idx & 1023;
            int rr = rem >> 5, k4 = rem & 31;
            const float* src = (arr ? h1in : h0in) + (rbase + rr) * 512 + k4 * 4;
            uint32_t dst = (arr ? hb1u0 : hb0u0) + (uint32_t)(rr * HCH + k4 * 4) * 4u;
            cpa16(dst, src);
        }
        CP_COMMIT();

        // gate-input prefetch (all lanes; hidden behind the dots)
        float xz = 0.f, xr = 0.f, xh = 0.f, h0o = 0.f, h1o = 0.f;
        if (t < T_STEPS) {
            size_t xb = ((size_t)t * G3 + ug) * BATCH + row;
            xz  = __ldg(&g_xg0[xb]);
            xr  = __ldg(&g_xg0[xb + 512 * BATCH]);
            xh  = __ldg(&g_xg0[xb + 1024 * BATCH]);
            h0o = __ldcg(h0in + row * 512 + ug);
        }
        if (t >= 1) h1o = __ldcg(h1in + row * 512 + ug);

        CP_WAIT0();
        __syncthreads();

        // ---- 8x9 register tile; kid owns k-quads it*8+kid (4 its/chunk) ----
        u64 acc[72] = {};   // [r*9 + j], k-pair packed
#pragma unroll
        for (int kc = 0; kc < 4; ++kc) {
            if (kc < 3) {   // async-stage next chunk into the other buffer
                uint32_t d0 = (kc & 1) ? hb0u0 : hb0u1;
                uint32_t d1 = (kc & 1) ? hb1u0 : hb1u1;
#pragma unroll
                for (int j = 0; j < 8; ++j) {
                    int idx = tid + j * TPB;
                    int arr = idx >> 10, rem = idx & 1023;
                    int rr = rem >> 5, k4 = rem & 31;
                    const float* src = (arr ? h1in : h0in) +
                                       (rbase + rr) * 512 + (kc + 1) * 128 + k4 * 4;
                    uint32_t dst = (arr ? d1 : d0) + (uint32_t)(rr * HCH + k4 * 4) * 4u;
                    cpa16(dst, src);
                }
                CP_COMMIT();
            }

            const float* hc0 = hb0[kc & 1] + rgi * 8 * HCH;
            const float* hc1 = hb1[kc & 1] + rgi * 8 * HCH;
            const float* wk  = wbase + kc * 128;
#pragma unroll
            for (int it = 0; it < 4; ++it) {
                int ko = (it * 8 + kid) * 4;          // float offset of this k-quad
                ulonglong2 W[9];
#pragma unroll
                for (int j = 0; j < 9; ++j)
                    W[j] = *(const ulonglong2*)(wk + j * WKS + ko);
#pragma unroll
                for (int r = 0; r < 8; ++r) {
                    ulonglong2 h0v = *(const ulonglong2*)(hc0 + r * HCH + ko);
                    ulonglong2 h1v = *(const ulonglong2*)(hc1 + r * HCH + ko);
#pragma unroll
                    for (int j = 0; j < 9; ++j) {
                        const bool useh1 = (j >= 3 && j < 6);
                        u64 alo = useh1 ? h1v.x : h0v.x;
                        u64 ahi = useh1 ? h1v.y : h0v.y;
                        FMA2(acc[r * 9 + j], alo, W[j].x);
                        FMA2(acc[r * 9 + j], ahi, W[j].y);
                    }
                }
            }

            if (kc < 3) {
                CP_WAIT0();
                __syncthreads();
            }
        }

        // ---- reduce k-split over kid (3 masked butterfly rounds) ----
        float vr[8][9];
#pragma unroll
        for (int r = 0; r < 8; ++r)
#pragma unroll
            for (int j = 0; j < 9; ++j) vr[r][j] = sum2(acc[r * 9 + j]);
#pragma unroll
        for (int B = 1; B <= 4; B <<= 1) {
#pragma unroll
            for (int r = 0; r < 8; ++r)
#pragma unroll
                for (int j = 0; j < 9; ++j) {
                    float o = __shfl_xor_sync(0xffffffffu, vr[r][j], B);
                    if (((r ^ kid) & B) == 0) vr[r][j] += o;
                }
        }
        float s[9];
#pragma unroll
        for (int r = 0; r < 8; ++r)
            if (r == kid) {
#pragma unroll
                for (int j = 0; j < 9; ++j) s[j] = vr[r][j];
            }

        // ---- pointwise (all lanes; r = kid -> row) ----
        if (t < T_STEPS) {
            float z    = sigf(xz + s[0] + br0z);
            float rgt  = sigf(xr + s[1] + br0r);
            float cand = tanhf(xh + rgt * (s[2] + br0h));
            h0out[row * 512 + ug] = z * h0o + (1.f - z) * cand;
        }
        if (t >= 1) {
            float z1    = sigf(s[6] + bi1z + s[3] + br1z);
            float r1    = sigf(s[7] + bi1r + s[4] + br1r);
            float cand1 = tanhf(s[8] + bi1h + r1 * (s[5] + br1h));
            float h1n   = z1 * h1o + (1.f - z1) * cand1;
            h1out[row * 512 + ug] = h1n;
            if (t == T_STEPS) out[row * 512 + ug] = h1n;
        }

        gbar(++gen);
    }
}

// ---------------- launcher ----------------
extern "C" void kernel_launch(void* const* d_in, const int* in_sizes, int n_in,
                              void* d_out, int out_size) {
    const float* x  = (const float*)d_in[0];
    const float* W0 = (const float*)d_in[1];
    const float* U0 = (const float*)d_in[2];
    const float* b0 = (const float*)d_in[3];
    const float* W1 = (const float*)d_in[4];
    const float* U1 = (const float*)d_in[5];
    const float* b1 = (const float*)d_in[6];
    float* out = (float*)d_out;

    cudaFuncSetAttribute(gru_loop, cudaFuncAttributeMaxDynamicSharedMemorySize,
                         SMEM_BYTES);

    precompute_xg0<<<dim3(24, 1024), PTPB>>>(x, W0, b0);
    gru_loop<<<NCTA, TPB, SMEM_BYTES>>>(U0, W1, U1, b0, b1, out);
}